// round 8
// baseline (speedup 1.0000x reference)
#include <cuda_runtime.h>
#include <cuda_fp16.h>
#include <cstdint>

#define THREADS 256
#define CTA_M   64
#define HROW    128                     // H row stride (words)
#define XSLOTW  4096                    // X slot: 64 rows x 64 words (2 chunks)
#define WOFFW   8192
#define WSLOTW  1024                    // per-warp W slot: 32 rows x 32 words
#define SMEM_WORDS (WOFFW + 16 * WSLOTW)   // 24576
#define SMEM_BYTES (SMEM_WORDS * 4)        // 98304 (2 CTAs/SM)

// pre-transposed, fp16, pair-interleaved weights: Wt[n][phys(k)]
__device__ __half g_W1t[256 * 512];
__device__ __half g_W2t[256 * 256];
__device__ __half g_W3t[128 * 256];

__device__ __forceinline__ uint32_t smem_u32(const void* p) {
    uint32_t a;
    asm("{ .reg .u64 t; cvta.to.shared.u64 t, %1; cvt.u32.u64 %0, t; }" : "=r"(a) : "l"(p));
    return a;
}
__device__ __forceinline__ float softplus_f(float x) {
    return (x > 20.0f) ? x : __logf(1.0f + __expf(x));
}
__device__ __forceinline__ uint32_t pack_h2(float lo, float hi) {
    __half2 h = __halves2half2(__float2half_rn(lo), __float2half_rn(hi));
    return *(uint32_t*)&h;
}
__device__ __forceinline__ void mma16(float* c, uint32_t a0, uint32_t a1,
                                      uint32_t a2, uint32_t a3,
                                      uint32_t b0, uint32_t b1) {
    asm volatile(
        "mma.sync.aligned.m16n8k16.row.col.f32.f16.f16.f32 "
        "{%0,%1,%2,%3}, {%4,%5,%6,%7}, {%8,%9}, {%0,%1,%2,%3};\n"
        : "+f"(c[0]), "+f"(c[1]), "+f"(c[2]), "+f"(c[3])
        : "r"(a0), "r"(a1), "r"(a2), "r"(a3), "r"(b0), "r"(b1));
}
__device__ __forceinline__ void cp16(uint32_t dst, const void* src) {
    asm volatile("cp.async.cg.shared.global [%0], [%1], 16;" :: "r"(dst), "l"(src) : "memory");
}
#define CP_COMMIT() asm volatile("cp.async.commit_group;" ::: "memory")
#define CP_WAIT1()  asm volatile("cp.async.wait_group 1;" ::: "memory")

// pair-interleaved physical half index (R7, unchanged)
__host__ __device__ __forceinline__ int phys_k(int k) {
    int w = k >> 1;
    int pw = (w & ~7) | (((w & 3) << 1) | ((w >> 2) & 1));
    return (pw << 1) | (k & 1);
}

// ---- GEMM over one 64-K chunk. A: rows [0,64) at stride astrw, cols at acol.
// B: per-warp private slot, 32-word rows, local rows nt*8+g.
template <int NT>
__device__ __forceinline__ void gemm64(float acc[4][NT][4],
                                       const uint32_t* sA, int astrw, int acol,
                                       const uint32_t* sB, int g, int t) {
    int xo = (g & 3) << 3;
#pragma unroll
    for (int gi = 0; gi < 4; gi++) {
        int off = (gi * 8 + 2 * t) ^ xo;
        uint32_t a[4][4];
#pragma unroll
        for (int mt = 0; mt < 4; mt++) {
            int r = mt * 16 + g;
            uint2 p0 = *(const uint2*)(sA + r * astrw + acol + off);
            uint2 p1 = *(const uint2*)(sA + (r + 8) * astrw + acol + off);
            a[mt][0] = p0.x; a[mt][2] = p0.y;
            a[mt][1] = p1.x; a[mt][3] = p1.y;
        }
#pragma unroll
        for (int nt = 0; nt < NT; nt++) {
            uint2 bb = *(const uint2*)(sB + (nt * 8 + g) * 32 + off);
#pragma unroll
            for (int mt = 0; mt < 4; mt++)
                mma16(acc[mt][nt], a[mt][0], a[mt][1], a[mt][2], a[mt][3], bb.x, bb.y);
        }
    }
}

// ---- X staging: one full 128-wide segment (2 chunks) for 64 edges ----
__device__ __forceinline__ void stage_x(uint32_t* x, int seg, long e0,
                                        const float* __restrict__ src,
                                        const float* __restrict__ dstp,
                                        const float* __restrict__ ea,
                                        const float* __restrict__ u,
                                        const void* __restrict__ batch, int b64, int tid) {
#pragma unroll
    for (int it = 0; it < 2; it++) {
        int task = tid + it * THREADS;     // 512: 64 rows x 8 k16-groups
        int row = task >> 3, gr = task & 7;
        const float* p;
        if (seg == 0)      p = src  + (e0 + row) * 128;
        else if (seg == 1) p = dstp + (e0 + row) * 128;
        else if (seg == 2) p = ea   + (e0 + row) * 128;
        else {
            long bi = b64 ? (long)((const long long*)batch)[e0 + row]
                          : (long)((const int*)batch)[e0 + row];
            p = u + bi * 128;
        }
        int off = gr * 16;
        float4 va = *(const float4*)(p + off);
        float4 vb = *(const float4*)(p + off + 8);
        float4 vc = *(const float4*)(p + off + 4);
        float4 vd = *(const float4*)(p + off + 12);
        int xo = (row & 3) << 3;
        uint4 o1 = make_uint4(pack_h2(va.x, va.y), pack_h2(vb.x, vb.y),
                              pack_h2(va.z, va.w), pack_h2(vb.z, vb.w));
        uint4 o2 = make_uint4(pack_h2(vc.x, vc.y), pack_h2(vd.x, vd.y),
                              pack_h2(vc.z, vc.w), pack_h2(vd.z, vd.w));
        *(uint4*)(x + row * 64 + ((gr * 8) ^ xo)) = o1;
        *(uint4*)(x + row * 64 + ((gr * 8 + 4) ^ xo)) = o2;
    }
}

// ---- per-warp W staging: NROWS rows (warp's own n-range) of one 64-K chunk ----
template <int NROWS>
__device__ __forceinline__ void stage_w_warp(uint32_t slot_byte,
                                             const __half* __restrict__ Wt,
                                             int n0w, int kfull, int kc, int lane) {
#pragma unroll
    for (int i = 0; i < (NROWS * 8) / 32; i++) {
        int task = lane + i * 32;
        int row = task >> 3, q = task & 7;
        uint32_t dst = slot_byte + (row * 32 + ((q * 4) ^ ((row & 3) << 3))) * 4;
        cp16(dst, Wt + (long)(n0w + row) * kfull + kc * 64 + q * 8);
    }
}

// ---- epilogue layers 1/2: bias + softplus -> half2 into H (R7 mapping) ----
template <int NT>
__device__ __forceinline__ void epi_h(float acc[4][NT][4], uint32_t* smw,
                                      const float* __restrict__ bias,
                                      int n0, int g, int t) {
#pragma unroll
    for (int nt = 0; nt < NT; nt++) {
        int c = n0 + nt * 8 + 2 * t;
        float bb0 = __ldg(bias + c);
        float bb1 = __ldg(bias + c + 1);
        int g8 = (c >> 1) >> 3;
        int pw = (g8 << 3) + 2 * t + (nt & 1);
#pragma unroll
        for (int mt = 0; mt < 4; mt++) {
            int r = mt * 16 + g;
            smw[r * HROW + (pw ^ ((r & 3) << 3))] =
                pack_h2(softplus_f(acc[mt][nt][0] + bb0), softplus_f(acc[mt][nt][1] + bb1));
            smw[(r + 8) * HROW + (pw ^ ((r & 3) << 3))] =
                pack_h2(softplus_f(acc[mt][nt][2] + bb0), softplus_f(acc[mt][nt][3] + bb1));
        }
    }
}

// ---- prepass: W [K][N] -> Wt [N][phys(K)] fp16 ----
__global__ void prep_w(const float* __restrict__ W, __half* __restrict__ Wt,
                       int K, int N) {
    __shared__ float tile[32][33];
    int kb = blockIdx.x * 32, nb = blockIdx.y * 32;
    int tx = threadIdx.x, ty = threadIdx.y;
    for (int i = ty; i < 32; i += 8)
        tile[i][tx] = W[(long)(kb + i) * N + nb + tx];
    __syncthreads();
    for (int i = ty; i < 32; i += 8)
        Wt[(long)(nb + i) * K + phys_k(kb + tx)] = __float2half_rn(tile[tx][i]);
}

__global__ void __launch_bounds__(THREADS, 2)
edge_mlp_v8(const float* __restrict__ src, const float* __restrict__ dstp,
            const float* __restrict__ ea, const float* __restrict__ u,
            const void* __restrict__ batch,
            const float* __restrict__ b1, const float* __restrict__ b2,
            const float* __restrict__ b3,
            float* __restrict__ out) {
    extern __shared__ uint32_t smw[];
    uint32_t sbyte = smem_u32(smw);

    int tid = threadIdx.x;
    int wid = tid >> 5;
    int lane = tid & 31;
    int g = lane >> 2;
    int t = lane & 3;
    int n0 = wid * 32;
    int n3 = wid * 16;
    long e0 = (long)blockIdx.x * CTA_M;

    const uint32_t* wslot[2] = { smw + WOFFW + wid * 2 * WSLOTW,
                                 smw + WOFFW + wid * 2 * WSLOTW + WSLOTW };
    uint32_t wb[2] = { sbyte + (WOFFW + wid * 2 * WSLOTW) * 4,
                       sbyte + (WOFFW + wid * 2 * WSLOTW + WSLOTW) * 4 };

    __shared__ int b64s;
    if (tid == 0) {
        const long long* p = (const long long*)batch;
        int f = 1;
        for (int i = 0; i < 16; i++) { long long v = p[i]; if (v < 0 || v >= 64) f = 0; }
        b64s = f;
    }
    __syncthreads();
    int b64 = b64s;

    float acc[4][4][4];
#pragma unroll
    for (int a = 0; a < 4; a++)
#pragma unroll
        for (int b = 0; b < 4; b++)
#pragma unroll
            for (int c = 0; c < 4; c++) acc[a][b][c] = 0.0f;

    // ============== Layer 1: K=512 (8 chunks), X in 4 segment windows =====
    stage_x(smw, 0, e0, src, dstp, ea, u, batch, b64, tid);
    stage_w_warp<32>(wb[0], g_W1t, n0, 512, 0, lane); CP_COMMIT();
    stage_w_warp<32>(wb[1], g_W1t, n0, 512, 1, lane); CP_COMMIT();
    __syncthreads();
#pragma unroll 1
    for (int kc = 0; kc < 8; kc++) {
        int sub = kc & 1, win = kc >> 1;
        if (sub == 0 && win < 3)
            stage_x(smw + ((win + 1) & 1) * XSLOTW, win + 1, e0,
                    src, dstp, ea, u, batch, b64, tid);
        CP_WAIT1();
        __syncwarp();
        gemm64<4>(acc, smw + (win & 1) * XSLOTW, 64, sub * 32, wslot[kc & 1], g, t);
        if (kc < 6) stage_w_warp<32>(wb[kc & 1], g_W1t, n0, 512, kc + 2, lane);
        else        stage_w_warp<32>(wb[kc & 1], g_W2t, n0, 256, kc - 6, lane);
        CP_COMMIT();
        if (sub == 1) __syncthreads();   // window boundary (last one = pre-epi)
    }
    epi_h<4>(acc, smw, b1, n0, g, t);
    __syncthreads();                      // publish H1

    // ============== Layer 2: K=256 (4 chunks), no block barriers ==========
#pragma unroll
    for (int a = 0; a < 4; a++)
#pragma unroll
        for (int b = 0; b < 4; b++)
#pragma unroll
            for (int c = 0; c < 4; c++) acc[a][b][c] = 0.0f;
#pragma unroll 1
    for (int kc = 0; kc < 4; kc++) {
        CP_WAIT1();
        __syncwarp();
        gemm64<4>(acc, smw, HROW, kc * 32, wslot[kc & 1], g, t);
        if (kc < 2) stage_w_warp<32>(wb[kc & 1], g_W2t, n0, 256, kc + 2, lane);
        else        stage_w_warp<16>(wb[kc & 1], g_W3t, n3, 256, kc - 2, lane);
        CP_COMMIT();
    }
    __syncthreads();                      // all H1 reads done
    epi_h<4>(acc, smw, b2, n0, g, t);
    __syncthreads();                      // publish H2

    // ============== Layer 3: K=256 (4 chunks), no block barriers ==========
    float acc3[4][2][4];
#pragma unroll
    for (int a = 0; a < 4; a++)
#pragma unroll
        for (int b = 0; b < 2; b++)
#pragma unroll
            for (int c = 0; c < 4; c++) acc3[a][b][c] = 0.0f;
#pragma unroll 1
    for (int kc = 0; kc < 4; kc++) {
        CP_WAIT1();
        __syncwarp();
        gemm64<2>(acc3, smw, HROW, kc * 32, wslot[kc & 1], g, t);
        if (kc < 2) stage_w_warp<16>(wb[kc & 1], g_W3t, n3, 256, kc + 2, lane);
        CP_COMMIT();
    }
    __syncthreads();                      // all H2 reads done

    // ---- output epilogue: f32 scratch (stride 132, spills into dead W) ----
    float* fH = (float*)smw;
#pragma unroll
    for (int nt = 0; nt < 2; nt++) {
        int c = n3 + nt * 8 + 2 * t;
        float bb0 = __ldg(b3 + c);
        float bb1 = __ldg(b3 + c + 1);
#pragma unroll
        for (int mt = 0; mt < 4; mt++) {
            int r = mt * 16 + g;
            *(float2*)(fH + r * 132 + c) =
                make_float2(acc3[mt][nt][0] + bb0, acc3[mt][nt][1] + bb1);
            *(float2*)(fH + (r + 8) * 132 + c) =
                make_float2(acc3[mt][nt][2] + bb0, acc3[mt][nt][3] + bb1);
        }
    }
    __syncthreads();
#pragma unroll
    for (int it = 0; it < 8; it++) {
        int task = tid + it * THREADS;
        int row = task >> 5, c4 = task & 31;
        *(float4*)(out + (e0 + row) * 128 + c4 * 4) =
            *(const float4*)(fH + row * 132 + c4 * 4);
    }
}

extern "C" void kernel_launch(void* const* d_in, const int* in_sizes, int n_in,
                              void* d_out, int out_size) {
    const float* src  = (const float*)d_in[0];
    const float* dstp = (const float*)d_in[1];
    const float* ea   = (const float*)d_in[2];
    const float* u    = (const float*)d_in[3];
    const void*  bat  = (const void*)d_in[4];
    const float* W1   = (const float*)d_in[5];
    const float* b1   = (const float*)d_in[6];
    const float* W2   = (const float*)d_in[7];
    const float* b2   = (const float*)d_in[8];
    const float* W3   = (const float*)d_in[9];
    const float* b3   = (const float*)d_in[10];
    float* out = (float*)d_out;

    cudaFuncSetAttribute(edge_mlp_v8,
                         cudaFuncAttributeMaxDynamicSharedMemorySize, SMEM_BYTES);

    __half *w1t, *w2t, *w3t;
    cudaGetSymbolAddress((void**)&w1t, g_W1t);
    cudaGetSymbolAddress((void**)&w2t, g_W2t);
    cudaGetSymbolAddress((void**)&w3t, g_W3t);
    dim3 blk(32, 8);
    prep_w<<<dim3(16, 8), blk>>>(W1, w1t, 512, 256);
    prep_w<<<dim3(8, 8),  blk>>>(W2, w2t, 256, 256);
    prep_w<<<dim3(8, 4),  blk>>>(W3, w3t, 256, 128);

    const int n_edges = in_sizes[4];
    const int grid = n_edges / CTA_M;   // 6250
    edge_mlp_v8<<<grid, THREADS, SMEM_BYTES>>>(src, dstp, ea, u, bat,
                                               b1, b2, b3, out);
}

// round 9
// speedup vs baseline: 1.1252x; 1.1252x over previous
#include <cuda_runtime.h>
#include <cuda_fp16.h>
#include <cstdint>

#define THREADS 256
#define CTA_M   64
#define HROW    128                     // H row stride (words); 64 rows at offset 0
#define XSLOTW  2048                    // X slot: 64 rows x 32 words (one 64-K chunk)
#define WOFFW   8192
#define WSLOTW  8192                    // W slot: 256 rows x 32 words
#define WSLOTB  (WSLOTW * 4)
#define SMEM_WORDS (WOFFW + 2 * WSLOTW) // 24576
#define SMEM_BYTES (SMEM_WORDS * 4)     // 98304 (2 CTAs/SM)

// pre-transposed fp16 weights, natural K-major: Wt[n][k]
__device__ __half g_W1t[256 * 512];
__device__ __half g_W2t[256 * 256];
__device__ __half g_W3t[128 * 256];

__device__ __forceinline__ uint32_t smem_u32(const void* p) {
    uint32_t a;
    asm("{ .reg .u64 t; cvta.to.shared.u64 t, %1; cvt.u32.u64 %0, t; }" : "=r"(a) : "l"(p));
    return a;
}
__device__ __forceinline__ float softplus_f(float x) {
    return (x > 20.0f) ? x : __logf(1.0f + __expf(x));
}
__device__ __forceinline__ uint32_t pack_h2(float lo, float hi) {
    __half2 h = __halves2half2(__float2half_rn(lo), __float2half_rn(hi));
    return *(uint32_t*)&h;
}
__device__ __forceinline__ void mma16(float* c, uint32_t a0, uint32_t a1,
                                      uint32_t a2, uint32_t a3,
                                      uint32_t b0, uint32_t b1) {
    asm volatile(
        "mma.sync.aligned.m16n8k16.row.col.f32.f16.f16.f32 "
        "{%0,%1,%2,%3}, {%4,%5,%6,%7}, {%8,%9}, {%0,%1,%2,%3};\n"
        : "+f"(c[0]), "+f"(c[1]), "+f"(c[2]), "+f"(c[3])
        : "r"(a0), "r"(a1), "r"(a2), "r"(a3), "r"(b0), "r"(b1));
}
__device__ __forceinline__ void ldsm4(uint32_t* r, uint32_t addr) {
    asm volatile("ldmatrix.sync.aligned.m8n8.x4.shared.b16 {%0,%1,%2,%3}, [%4];"
        : "=r"(r[0]), "=r"(r[1]), "=r"(r[2]), "=r"(r[3]) : "r"(addr));
}
__device__ __forceinline__ void cp16(uint32_t dst, const void* src) {
    asm volatile("cp.async.cg.shared.global [%0], [%1], 16;" :: "r"(dst), "l"(src) : "memory");
}
#define CP_COMMIT() asm volatile("cp.async.commit_group;" ::: "memory")
#define CP_WAIT1()  asm volatile("cp.async.wait_group 1;" ::: "memory")

// ---- GEMM over one 64-K chunk via ldmatrix. Warp tile 64M x (NTP*16)N.
// A rows [0,64) at aBase, row stride arowB bytes, unit base aub (=8*kc for H).
// B at bBase (lane-resolved n row base), 128B rows.
template <int NTP>
__device__ __forceinline__ void gemm64(float acc[4][2 * NTP][4],
                                       uint32_t aBase, int arowB, int aub,
                                       uint32_t bBase, int lane) {
    int rw = lane & 7;
    int duA = (lane >> 4) & 1;
    int duB = (lane >> 3) & 1;
    uint32_t aL = aBase + (uint32_t)((((lane >> 3) & 1) * 8 + rw) * arowB);
#pragma unroll
    for (int gi = 0; gi < 4; gi++) {
        uint32_t uA = (uint32_t)(aub + ((2 * gi + duA) ^ rw)) << 4;
        uint32_t a[4][4];
#pragma unroll
        for (int mt = 0; mt < 4; mt++)
            ldsm4(a[mt], aL + mt * 16 * arowB + uA);
        uint32_t uB = (uint32_t)((2 * gi + duB) ^ rw) << 4;
#pragma unroll
        for (int ntp = 0; ntp < NTP; ntp++) {
            uint32_t b[4];
            ldsm4(b, bBase + ntp * (16 * 128) + uB);
#pragma unroll
            for (int mt = 0; mt < 4; mt++) {
                mma16(acc[mt][2 * ntp],     a[mt][0], a[mt][1], a[mt][2], a[mt][3], b[0], b[1]);
                mma16(acc[mt][2 * ntp + 1], a[mt][0], a[mt][1], a[mt][2], a[mt][3], b[2], b[3]);
            }
        }
    }
}

// ---- X staging: one 64-K chunk for 64 edges, natural order + unit swizzle ----
__device__ __forceinline__ void stage_x(uint32_t* x, int kc, long e0,
                                        const float* __restrict__ src,
                                        const float* __restrict__ dstp,
                                        const float* __restrict__ ea,
                                        const float* __restrict__ u,
                                        const void* __restrict__ batch, int b64, int tid) {
    int row = tid >> 2, q = tid & 3;
    int k0 = kc * 64, seg = k0 >> 7, off = (k0 & 127) + q * 16;
    const float* p;
    if (seg == 0)      p = src  + (e0 + row) * 128;
    else if (seg == 1) p = dstp + (e0 + row) * 128;
    else if (seg == 2) p = ea   + (e0 + row) * 128;
    else {
        long bi = b64 ? (long)((const long long*)batch)[e0 + row]
                      : (long)((const int*)batch)[e0 + row];
        p = u + bi * 128;
    }
    float4 f0 = *(const float4*)(p + off);
    float4 f1 = *(const float4*)(p + off + 4);
    float4 f2 = *(const float4*)(p + off + 8);
    float4 f3 = *(const float4*)(p + off + 12);
    uint4 o1 = make_uint4(pack_h2(f0.x, f0.y), pack_h2(f0.z, f0.w),
                          pack_h2(f1.x, f1.y), pack_h2(f1.z, f1.w));
    uint4 o2 = make_uint4(pack_h2(f2.x, f2.y), pack_h2(f2.z, f2.w),
                          pack_h2(f3.x, f3.y), pack_h2(f3.z, f3.w));
    int rm = row & 7;
    *(uint4*)(x + row * 32 + (((2 * q) ^ rm) << 2)) = o1;
    *(uint4*)(x + row * 32 + (((2 * q + 1) ^ rm) << 2)) = o2;
}

// ---- W staging: 64-K chunk via cp.async (16B units), swizzled dst ----
template <int NROWS, int KFULL>
__device__ __forceinline__ void stage_w(uint32_t wbase_byte, const __half* __restrict__ Wt,
                                        int kc, int tid) {
#pragma unroll
    for (int it = 0; it < (NROWS * 8) / THREADS; it++) {
        int task = tid + it * THREADS;
        int row = task >> 3, q = task & 7;
        uint32_t dst = wbase_byte + (row * 32 + ((q ^ (row & 7)) << 2)) * 4;
        cp16(dst, Wt + (long)row * KFULL + kc * 64 + q * 8);
    }
}

// ---- epilogue layers 1/2: bias + softplus -> half2 into H (natural+swizzle) ----
template <int NT>
__device__ __forceinline__ void epi_h(float acc[4][NT][4], uint32_t* smw,
                                      const float* __restrict__ bias,
                                      int n0, int g, int t) {
#pragma unroll
    for (int nt = 0; nt < NT; nt++) {
        int c = n0 + nt * 8 + 2 * t;
        float bb0 = __ldg(bias + c);
        float bb1 = __ldg(bias + c + 1);
        int uu = (n0 >> 3) + nt;
        int w = ((uu ^ g) << 2) + t;   // (r&7)==g for all rows below
#pragma unroll
        for (int mt = 0; mt < 4; mt++) {
            int r = mt * 16 + g;
            smw[r * HROW + w] =
                pack_h2(softplus_f(acc[mt][nt][0] + bb0), softplus_f(acc[mt][nt][1] + bb1));
            smw[(r + 8) * HROW + w] =
                pack_h2(softplus_f(acc[mt][nt][2] + bb0), softplus_f(acc[mt][nt][3] + bb1));
        }
    }
}

// ---- prepass: W [K][N] -> Wt [N][K] fp16 (plain transpose) ----
__global__ void prep_w(const float* __restrict__ W, __half* __restrict__ Wt,
                       int K, int N) {
    __shared__ float tile[32][33];
    int kb = blockIdx.x * 32, nb = blockIdx.y * 32;
    int tx = threadIdx.x, ty = threadIdx.y;
    for (int i = ty; i < 32; i += 8)
        tile[i][tx] = W[(long)(kb + i) * N + nb + tx];
    __syncthreads();
    for (int i = ty; i < 32; i += 8)
        Wt[(long)(nb + i) * K + kb + tx] = __float2half_rn(tile[tx][i]);
}

__global__ void __launch_bounds__(THREADS, 2)
edge_mlp_v9(const float* __restrict__ src, const float* __restrict__ dstp,
            const float* __restrict__ ea, const float* __restrict__ u,
            const void* __restrict__ batch,
            const float* __restrict__ b1, const float* __restrict__ b2,
            const float* __restrict__ b3,
            float* __restrict__ out) {
    extern __shared__ uint32_t smw[];
    uint32_t sbyte = smem_u32(smw);

    int tid = threadIdx.x;
    int wid = tid >> 5;
    int lane = tid & 31;
    int g = lane >> 2;
    int t = lane & 3;
    int n0 = wid * 32;
    int n3 = wid * 16;
    long e0 = (long)blockIdx.x * CTA_M;

    uint32_t wb[2] = { sbyte + WOFFW * 4, sbyte + WOFFW * 4 + WSLOTB };
    // lane-resolved B row bases (row = n + (lane>>4)*8 + (lane&7), 128B rows)
    uint32_t bL12 = sbyte + WOFFW * 4 + (uint32_t)((n0 + ((lane >> 4) & 1) * 8 + (lane & 7)) * 128);
    uint32_t bL3  = sbyte + WOFFW * 4 + (uint32_t)((n3 + ((lane >> 4) & 1) * 8 + (lane & 7)) * 128);

    __shared__ int b64s;
    if (tid == 0) {
        const long long* p = (const long long*)batch;
        int f = 1;
        for (int i = 0; i < 16; i++) { long long v = p[i]; if (v < 0 || v >= 64) f = 0; }
        b64s = f;
    }
    __syncthreads();
    int b64 = b64s;

    float acc[4][4][4];
#pragma unroll
    for (int a = 0; a < 4; a++)
#pragma unroll
        for (int b = 0; b < 4; b++)
#pragma unroll
            for (int c = 0; c < 4; c++) acc[a][b][c] = 0.0f;

    // ============== Layer 1: K=512 (8 chunks of 64), N=256 ================
    stage_x(smw, 0, e0, src, dstp, ea, u, batch, b64, tid);
    stage_w<256, 512>(wb[0], g_W1t, 0, tid);
    CP_COMMIT();
    stage_x(smw + XSLOTW, 1, e0, src, dstp, ea, u, batch, b64, tid);
    stage_w<256, 512>(wb[1], g_W1t, 1, tid);
    CP_COMMIT();
#pragma unroll 1
    for (int kc = 0; kc < 8; kc++) {
        int s = kc & 1;
        CP_WAIT1();
        __syncthreads();
        gemm64<2>(acc, sbyte + s * (XSLOTW * 4), 128, 0, bL12 + s * WSLOTB, lane);
        __syncthreads();
        if (kc < 6) {
            stage_x(smw + s * XSLOTW, kc + 2, e0, src, dstp, ea, u, batch, b64, tid);
            stage_w<256, 512>(wb[s], g_W1t, kc + 2, tid);
        } else {
            stage_w<256, 256>(wb[s], g_W2t, kc - 6, tid);   // prefetch W2
        }
        CP_COMMIT();
    }
    epi_h<4>(acc, smw, b1, n0, g, t);
    __syncthreads();                      // publish H1

    // ============== Layer 2: K=256 (4 chunks), N=256, A = H ===============
#pragma unroll
    for (int a = 0; a < 4; a++)
#pragma unroll
        for (int b = 0; b < 4; b++)
#pragma unroll
            for (int c = 0; c < 4; c++) acc[a][b][c] = 0.0f;
#pragma unroll 1
    for (int kc = 0; kc < 4; kc++) {
        int s = kc & 1;
        CP_WAIT1();
        __syncthreads();
        gemm64<2>(acc, sbyte, 512, 8 * kc, bL12 + s * WSLOTB, lane);
        __syncthreads();
        if (kc < 2) stage_w<256, 256>(wb[s], g_W2t, kc + 2, tid);
        else        stage_w<128, 256>(wb[s], g_W3t, kc - 2, tid);   // prefetch W3
        CP_COMMIT();
    }
    epi_h<4>(acc, smw, b2, n0, g, t);
    __syncthreads();                      // publish H2

    // ============== Layer 3: K=256 (4 chunks), N=128, A = H ===============
    float acc3[4][2][4];
#pragma unroll
    for (int a = 0; a < 4; a++)
#pragma unroll
        for (int b = 0; b < 2; b++)
#pragma unroll
            for (int c = 0; c < 4; c++) acc3[a][b][c] = 0.0f;
#pragma unroll 1
    for (int kc = 0; kc < 4; kc++) {
        int s = kc & 1;
        CP_WAIT1();
        __syncthreads();
        gemm64<1>(acc3, sbyte, 512, 8 * kc, bL3 + s * WSLOTB, lane);
        __syncthreads();
        if (kc < 2) stage_w<128, 256>(wb[s], g_W3t, kc + 2, tid);
        CP_COMMIT();
    }

    // ---- output epilogue: f32 scratch (stride 132 over dead H/X/W) ----
    float* fH = (float*)smw;
#pragma unroll
    for (int nt = 0; nt < 2; nt++) {
        int c = n3 + nt * 8 + 2 * t;
        float bb0 = __ldg(b3 + c);
        float bb1 = __ldg(b3 + c + 1);
#pragma unroll
        for (int mt = 0; mt < 4; mt++) {
            int r = mt * 16 + g;
            *(float2*)(fH + r * 132 + c) =
                make_float2(acc3[mt][nt][0] + bb0, acc3[mt][nt][1] + bb1);
            *(float2*)(fH + (r + 8) * 132 + c) =
                make_float2(acc3[mt][nt][2] + bb0, acc3[mt][nt][3] + bb1);
        }
    }
    __syncthreads();
#pragma unroll
    for (int it = 0; it < 8; it++) {
        int task = tid + it * THREADS;
        int row = task >> 5, c4 = task & 31;
        *(float4*)(out + (e0 + row) * 128 + c4 * 4) =
            *(const float4*)(fH + row * 132 + c4 * 4);
    }
}

extern "C" void kernel_launch(void* const* d_in, const int* in_sizes, int n_in,
                              void* d_out, int out_size) {
    const float* src  = (const float*)d_in[0];
    const float* dstp = (const float*)d_in[1];
    const float* ea   = (const float*)d_in[2];
    const float* u    = (const float*)d_in[3];
    const void*  bat  = (const void*)d_in[4];
    const float* W1   = (const float*)d_in[5];
    const float* b1   = (const float*)d_in[6];
    const float* W2   = (const float*)d_in[7];
    const float* b2   = (const float*)d_in[8];
    const float* W3   = (const float*)d_in[9];
    const float* b3   = (const float*)d_in[10];
    float* out = (float*)d_out;

    cudaFuncSetAttribute(edge_mlp_v9,
                         cudaFuncAttributeMaxDynamicSharedMemorySize, SMEM_BYTES);

    __half *w1t, *w2t, *w3t;
    cudaGetSymbolAddress((void**)&w1t, g_W1t);
    cudaGetSymbolAddress((void**)&w2t, g_W2t);
    cudaGetSymbolAddress((void**)&w3t, g_W3t);
    dim3 blk(32, 8);
    prep_w<<<dim3(16, 8), blk>>>(W1, w1t, 512, 256);
    prep_w<<<dim3(8, 8),  blk>>>(W2, w2t, 256, 256);
    prep_w<<<dim3(8, 4),  blk>>>(W3, w3t, 256, 128);

    const int n_edges = in_sizes[4];
    const int grid = n_edges / CTA_M;   // 6250
    edge_mlp_v9<<<grid, THREADS, SMEM_BYTES>>>(src, dstp, ea, u, bat,
                                               b1, b2, b3, out);
}